// round 9
// baseline (speedup 1.0000x reference)
#include <cuda_runtime.h>
#include <math.h>
#include <float.h>

#define G 32
#define GC (G * G * G)
#define NB 4       // batches
#define NCB 8      // cloud*NB + b
#define NPC 8192   // max points per (cloud,batch)
#define GMIN (-5.0f)
#define GH 0.3125f        // 10/32
#define GINV 3.2f         // 32/10
#define SEGS 32           // scan segments per cb
#define SEGC (GC / SEGS)  // 1024 cells per segment

// Static scratch (no cudaMalloc anywhere).
__device__ int g_cnt[NCB][GC];
__device__ int g_start[NCB][GC + 1];
__device__ int g_segtot[NCB][SEGS];
__device__ int g_cid[NCB][NPC];
__device__ int g_rnk[NCB][NPC];
__device__ float4 g_pts[NCB][NPC];  // cell-sorted (x, y, z, |p|^2/2)
__device__ float g_part[1024];
__device__ unsigned g_barcnt = 0;
__device__ unsigned g_bargen = 0;

// Self-resetting grid barrier (all blocks resident: grid << capacity).
__device__ __forceinline__ void gridbar() {
    __syncthreads();
    if (threadIdx.x == 0) {
        __threadfence();
        unsigned gen = atomicAdd(&g_bargen, 0u);
        if (atomicAdd(&g_barcnt, 1u) == gridDim.x - 1) {
            atomicExch(&g_barcnt, 0u);
            __threadfence();
            atomicAdd(&g_bargen, 1u);
        } else {
            while (atomicAdd(&g_bargen, 0u) == gen) __nanosleep(64);
        }
        __threadfence();
    }
    __syncthreads();
}

__device__ __forceinline__ int cellof(float x) {
    int c = (int)((x - GMIN) * GINV);
    return min(G - 1, max(0, c));
}

__global__ __launch_bounds__(256) void fused_kernel(const float* __restrict__ in1,
                                                    const float* __restrict__ in2,
                                                    float* __restrict__ out,
                                                    int N, int M) {
    const int tid = threadIdx.x;
    const int gid = blockIdx.x * 256 + tid;
    const int gsz = gridDim.x * 256;
    const int tot1 = NB * N;
    const int total = tot1 + NB * M;

    __shared__ int shi[256];
    __shared__ int shOff;
    __shared__ float shf[8];

    // ---- Phase Z: zero counters ----
    for (int j = gid; j < NCB * GC; j += gsz) ((int*)g_cnt)[j] = 0;
    gridbar();

    // ---- Phase C: bin points (cell id + rank) ----
    for (int i = gid; i < total; i += gsz) {
        const float* p;
        int cb, slot;
        if (i < tot1) { cb = i / N; slot = i - cb * N; p = in1 + (size_t)i * 3; }
        else {
            int j = i - tot1;
            cb = NB + j / M;
            slot = j - (cb - NB) * M;
            p = in2 + (size_t)j * 3;
        }
        int cid = (cellof(p[2]) * G + cellof(p[1])) * G + cellof(p[0]);
        g_cid[cb][slot] = cid;
        g_rnk[cb][slot] = atomicAdd(&g_cnt[cb][cid], 1);
    }
    gridbar();

    // ---- Phase S1: segment-local exclusive scan (NCB*SEGS = 256 segments) ----
    for (int w = blockIdx.x; w < NCB * SEGS; w += gridDim.x) {
        const int cb = w >> 5, seg = w & 31;
        const int cbase = seg * SEGC + tid * 4;
        const int c0 = g_cnt[cb][cbase], c1 = g_cnt[cb][cbase + 1];
        const int c2 = g_cnt[cb][cbase + 2], c3 = g_cnt[cb][cbase + 3];
        const int tsum = c0 + c1 + c2 + c3;
        shi[tid] = tsum;
        __syncthreads();
        for (int off = 1; off < 256; off <<= 1) {
            int v = (tid >= off) ? shi[tid - off] : 0;
            __syncthreads();
            shi[tid] += v;
            __syncthreads();
        }
        const int excl = shi[tid] - tsum;
        g_start[cb][cbase] = excl;
        g_start[cb][cbase + 1] = excl + c0;
        g_start[cb][cbase + 2] = excl + c0 + c1;
        g_start[cb][cbase + 3] = excl + c0 + c1 + c2;
        if (tid == 255) g_segtot[cb][seg] = shi[255];
        __syncthreads();
    }
    gridbar();

    // ---- Phase S2: add per-segment offsets; write sentinel ----
    for (int w = blockIdx.x; w < NCB * SEGS; w += gridDim.x) {
        const int cb = w >> 5, seg = w & 31;
        if (tid == 0) {
            int off = 0;
            for (int s = 0; s < seg; s++) off += g_segtot[cb][s];
            shOff = off;
        }
        __syncthreads();
        const int off = shOff;
        const int cbase = seg * SEGC + tid * 4;
        g_start[cb][cbase] += off;
        g_start[cb][cbase + 1] += off;
        g_start[cb][cbase + 2] += off;
        g_start[cb][cbase + 3] += off;
        if (seg == SEGS - 1 && tid == 0) g_start[cb][GC] = (cb < NB) ? N : M;
        __syncthreads();
    }
    gridbar();

    // ---- Phase SC: scatter into cell-sorted order ----
    for (int i = gid; i < total; i += gsz) {
        const float* p;
        int cb, slot;
        if (i < tot1) { cb = i / N; slot = i - cb * N; p = in1 + (size_t)i * 3; }
        else {
            int j = i - tot1;
            cb = NB + j / M;
            slot = j - (cb - NB) * M;
            p = in2 + (size_t)j * 3;
        }
        const float x = p[0], y = p[1], z = p[2];
        const int pos = g_start[cb][g_cid[cb][slot]] + g_rnk[cb][slot];
        g_pts[cb][pos] = make_float4(x, y, z, 0.5f * (x * x + y * y + z * z));
    }
    gridbar();

    // ---- Phase SR: exact NN search (contiguous row ranges) + block partial sum ----
    const float inv1 = 1.f / (float)(NB * N);
    const float inv0 = 1.f / (float)(NB * M);
    float contrib = 0.f;
    for (int i = gid; i < total; i += gsz) {
        int qcb, rcb;
        float wgt;
        if (i < tot1) { qcb = i / N; rcb = NB + qcb; wgt = inv1; }
        else { int j = i - tot1; qcb = NB + j / M; rcb = qcb - NB; wgt = inv0; }
        const int slot = (i < tot1) ? (i % N) : ((i - tot1) % M);

        const float4 q = g_pts[qcb][slot];  // sorted order -> warp-coherent cells
        const float nqx = -q.x, nqy = -q.y, nqz = -q.z, gq = q.w;
        const int cx = cellof(q.x), cy = cellof(q.y), cz = cellof(q.z);

        const float4* __restrict__ pts = g_pts[rcb];
        const int* __restrict__ cs = g_start[rcb];

        float tmin = FLT_MAX;
        float best;
        int R = 1;
        for (;; R++) {
            const int z0 = max(cz - R, 0), z1 = min(cz + R, G - 1);
            const int y0 = max(cy - R, 0), y1 = min(cy + R, G - 1);
            const int x0 = max(cx - R, 0), x1 = min(cx + R, G - 1);
            for (int z = z0; z <= z1; z++) {
                for (int y = y0; y <= y1; y++) {
                    const int rowb = (z * G + y) * G;
                    const int s = cs[rowb + x0];
                    const int e = cs[rowb + x1 + 1];
                    for (int k = s; k < e; k++) {
                        float4 p = pts[k];
                        float t = fmaf(p.x, nqx, fmaf(p.y, nqy, fmaf(p.z, nqz, p.w)));
                        tmin = fminf(tmin, t);
                    }
                }
            }
            best = fmaxf(0.f, 2.f * (tmin + gq));
            const float bd = (float)R * GH;  // unscanned points are >= R*GH away
            if (best <= bd * bd || R >= G) break;
        }
        contrib += sqrtf(best) * wgt;
    }

    // Deterministic per-block reduction (fixed thread->query mapping).
    float acc = contrib;
#pragma unroll
    for (int off = 16; off > 0; off >>= 1)
        acc += __shfl_down_sync(0xFFFFFFFFu, acc, off);
    if ((tid & 31) == 0) shf[tid >> 5] = acc;
    __syncthreads();
    if (tid < 8) {
        float v = shf[tid];
#pragma unroll
        for (int off = 4; off > 0; off >>= 1)
            v += __shfl_down_sync(0xFFu, v, off);
        if (tid == 0) g_part[blockIdx.x] = v;
    }
    gridbar();

    // ---- Phase F: block 0 sums partials (fixed order) ----
    if (blockIdx.x == 0) {
        float a = 0.f;
        for (int k = tid; k < (int)gridDim.x; k += 256) a += g_part[k];
#pragma unroll
        for (int off = 16; off > 0; off >>= 1)
            a += __shfl_down_sync(0xFFFFFFFFu, a, off);
        if ((tid & 31) == 0) shf[tid >> 5] = a;
        __syncthreads();
        if (tid < 8) {
            float v = shf[tid];
#pragma unroll
            for (int off = 4; off > 0; off >>= 1)
                v += __shfl_down_sync(0xFFu, v, off);
            if (tid == 0) out[0] = v;
        }
    }
}

extern "C" void kernel_launch(void* const* d_in, const int* in_sizes, int n_in,
                              void* d_out, int out_size) {
    const float* in1 = (const float*)d_in[0];  // [B, N, 3] cloud1
    const float* in2 = (const float*)d_in[1];  // [B, M, 3] cloud2
    const int N = in_sizes[0] / (NB * 3);
    const int M = in_sizes[1] / (NB * 3);
    const int total = NB * (N + M);
    int nBlocks = (total + 255) / 256;  // 256 for the 8192/8192 shape
    if (nBlocks > 512) nBlocks = 512;   // keep all blocks co-resident
    fused_kernel<<<nBlocks, 256>>>(in1, in2, (float*)d_out, N, M);
}